// round 5
// baseline (speedup 1.0000x reference)
#include <cuda_runtime.h>
#include <cstdint>

#define NJ 50
#define EDIM 192
#define ETSTRIDE 56      // floats per k-row of Et; js-bases {0,14,28,42} -> distinct banks
#define ROWS_PER_WARP 64
#define NWARP 8
#define NTHREADS 256
#define ROWS_PER_BLOCK 512

__device__ double g_loss_sum;     // zero-init at module load
__device__ unsigned int g_done;

static __device__ __forceinline__ unsigned long long pack2(float lo, float hi) {
    unsigned long long r;
    asm("mov.b64 %0, {%1, %2};" : "=l"(r) : "f"(lo), "f"(hi));
    return r;
}
static __device__ __forceinline__ unsigned long long pack2s(float v) {
    unsigned long long r;
    asm("mov.b64 %0, {%1, %1};" : "=l"(r) : "f"(v));
    return r;
}
static __device__ __forceinline__ void unpack2(unsigned long long v, float& lo, float& hi) {
    asm("mov.b64 {%0, %1}, %2;" : "=f"(lo), "=f"(hi) : "l"(v));
}
// Packed dual fp32 FMA (FFMA2)
static __device__ __forceinline__ unsigned long long fma2(unsigned long long a,
                                                          unsigned long long b,
                                                          unsigned long long c) {
    unsigned long long d;
    asm("fma.rn.f32x2 %0, %1, %2, %3;" : "=l"(d) : "l"(a), "l"(b), "l"(c));
    return d;
}

// Thread layout: lane = (g<<2)|js ; js in [0,4) = code-split, g in [0,8) = row group.
// Thread rows: base + g + 8*i, i=0..7. Codes: j = 13*js + jj, jj in [0,13).
// j=50,51 are dummies (e slots zero, see=+inf).
__global__ void __launch_bounds__(NTHREADS, 1) vq_kernel(
        const float* __restrict__ x, const float* __restrict__ e,
        float* __restrict__ out, int n) {
    __shared__ float Et[EDIM * ETSTRIDE];   // Et[k*56 + 14*js + jj] = e[13js+jj][k]
    __shared__ float see[52];
    __shared__ int   bjsh[ROWS_PER_BLOCK];
    __shared__ float wred[NWARP];

    const int tid = threadIdx.x;
    const int wid = tid >> 5;
    const int lane = tid & 31;
    const int js = lane & 3;
    const int g = lane >> 2;

    // ---- init: zero Et, fill transposed codebook, see (+inf pads) ----
    for (int i = tid; i < EDIM * ETSTRIDE; i += NTHREADS) Et[i] = 0.f;
    __syncthreads();
    for (int i = tid; i < NJ * EDIM; i += NTHREADS) {
        int j = i / EDIM, k = i - j * EDIM;        // e[j][k] coalesced read
        int jsp = j / 13; if (jsp > 3) jsp = 3;
        int jj = j - 13 * jsp;
        Et[k * ETSTRIDE + 14 * jsp + jj] = e[i];
    }
    if (tid < 52) {
        float s = 3.402823466e38f;
        if (tid < NJ) {
            s = 0.f;
            const float* ej = e + (size_t)tid * EDIM;
            #pragma unroll 4
            for (int k = 0; k < EDIM; ++k) { float v = __ldg(ej + k); s = fmaf(v, v, s); }
        }
        see[tid] = s;
    }
    __syncthreads();

    const int tile_base = blockIdx.x * ROWS_PER_BLOCK;
    const int warpbase = wid * ROWS_PER_WARP;
    int rows[8];
    #pragma unroll
    for (int i = 0; i < 8; ++i) {
        int r = tile_base + warpbase + g + 8 * i;
        rows[i] = (r < n) ? r : (n - 1);
    }

    // ---- accumulate 8 rows x 13 codes + per-row ||x||^2 (R2's exact chain) ----
    unsigned long long acc[4][13];
    unsigned long long ss0[4], ss1[4];      // ||x||^2 partials: s0 <- x,z ; s1 <- y,w
    #pragma unroll
    for (int p = 0; p < 4; ++p) {
        ss0[p] = 0ULL; ss1[p] = 0ULL;
        #pragma unroll
        for (int jj = 0; jj < 13; ++jj) acc[p][jj] = 0ULL;
    }

    const float4* x4 = reinterpret_cast<const float4*>(x);
    const int ebase = 14 * js;

    #pragma unroll 1
    for (int kq = 0; kq < EDIM / 4; ++kq) {
        float4 xv[8];
        #pragma unroll
        for (int i = 0; i < 8; ++i) xv[i] = __ldg(x4 + (size_t)rows[i] * 48 + kq);

        #pragma unroll
        for (int c = 0; c < 4; ++c) {
            const int k = kq * 4 + c;
            const float* erow = &Et[k * ETSTRIDE + ebase];
            unsigned long long ep[13];
            #pragma unroll
            for (int jj = 0; jj < 13; ++jj) ep[jj] = pack2s(erow[jj]);
            float a0, a1, a2, a3, a4, a5, a6, a7;
            if (c == 0)      { a0=xv[0].x; a1=xv[1].x; a2=xv[2].x; a3=xv[3].x; a4=xv[4].x; a5=xv[5].x; a6=xv[6].x; a7=xv[7].x; }
            else if (c == 1) { a0=xv[0].y; a1=xv[1].y; a2=xv[2].y; a3=xv[3].y; a4=xv[4].y; a5=xv[5].y; a6=xv[6].y; a7=xv[7].y; }
            else if (c == 2) { a0=xv[0].z; a1=xv[1].z; a2=xv[2].z; a3=xv[3].z; a4=xv[4].z; a5=xv[5].z; a6=xv[6].z; a7=xv[7].z; }
            else             { a0=xv[0].w; a1=xv[1].w; a2=xv[2].w; a3=xv[3].w; a4=xv[4].w; a5=xv[5].w; a6=xv[6].w; a7=xv[7].w; }
            unsigned long long xp[4];
            xp[0] = pack2(a0, a1); xp[1] = pack2(a2, a3);
            xp[2] = pack2(a4, a5); xp[3] = pack2(a6, a7);
            // ||x||^2 partials: components x,z -> s0 ; y,w -> s1 (matches R2's order)
            if ((c & 1) == 0) {
                #pragma unroll
                for (int p = 0; p < 4; ++p) ss0[p] = fma2(xp[p], xp[p], ss0[p]);
            } else {
                #pragma unroll
                for (int p = 0; p < 4; ++p) ss1[p] = fma2(xp[p], xp[p], ss1[p]);
            }
            #pragma unroll
            for (int jj = 0; jj < 13; ++jj) {
                acc[0][jj] = fma2(xp[0], ep[jj], acc[0][jj]);
                acc[1][jj] = fma2(xp[1], ep[jj], acc[1][jj]);
                acc[2][jj] = fma2(xp[2], ep[jj], acc[2][jj]);
                acc[3][jj] = fma2(xp[3], ep[jj], acc[3][jj]);
            }
        }
    }

    // ---- per-thread argmin with the R2-exact comparison:
    //      t = __fsub_rn(__fadd_rn(sxx, see_j), 2*dot) ----
    float bv[8];
    int   bjx[8];
    #pragma unroll
    for (int p = 0; p < 4; ++p) {
        float s0lo, s0hi, s1lo, s1hi;
        unpack2(ss0[p], s0lo, s0hi);
        unpack2(ss1[p], s1lo, s1hi);
        const float sxlo = s0lo + s1lo;      // row i = 2p
        const float sxhi = s0hi + s1hi;      // row i = 2p+1
        float v0 = 3.402823466e38f, v1 = 3.402823466e38f;
        int j0 = 0, j1 = 0;
        #pragma unroll
        for (int jj = 0; jj < 13; ++jj) {
            const int j = 13 * js + jj;
            const float sj = see[j];
            float dlo, dhi;
            unpack2(acc[p][jj], dlo, dhi);
            float m0 = __fsub_rn(__fadd_rn(sxlo, sj), 2.0f * dlo);
            float m1 = __fsub_rn(__fadd_rn(sxhi, sj), 2.0f * dhi);
            if (m0 < v0) { v0 = m0; j0 = j; }
            if (m1 < v1) { v1 = m1; j1 = j; }
        }
        bv[2 * p] = v0;     bjx[2 * p] = j0;
        bv[2 * p + 1] = v1; bjx[2 * p + 1] = j1;
    }
    // combine across the 4 js-lanes (lane bits 0,1); lexicographic => first-index ties
    #pragma unroll
    for (int i = 0; i < 8; ++i) {
        float v = bv[i]; int jx = bjx[i];
        #pragma unroll
        for (int mask = 1; mask <= 2; mask <<= 1) {
            float ov = __shfl_xor_sync(0xffffffffu, v, mask);
            int   oj = __shfl_xor_sync(0xffffffffu, jx, mask);
            if (ov < v || (ov == v && oj < jx)) { v = ov; jx = oj; }
        }
        const int grow = tile_base + warpbase + g + 8 * i;
        if (js == 0) {
            bjsh[warpbase + g + 8 * i] = jx;
            if (grow < n) out[(size_t)n * EDIM + grow] = (float)jx;
        }
    }
    __syncwarp();

    // ---- phase 2: warp-cooperative coalesced straight-through write + loss ----
    float lsum = 0.f;
    const float4* e4 = reinterpret_cast<const float4*>(e);
    float4* o4 = reinterpret_cast<float4*>(out);
    #pragma unroll 4
    for (int it = 0; it < (ROWS_PER_WARP * 48) / 32; ++it) {   // 96 iters
        const int idx = it * 32 + lane;
        const int rl = idx / 48, c4 = idx - rl * 48;
        const int grow = tile_base + warpbase + rl;
        if (grow < n) {
            const int bj = bjsh[warpbase + rl];
            const float4 xq = __ldg(x4 + (size_t)grow * 48 + c4);
            const float4 qq = __ldg(e4 + (size_t)bj * 48 + c4);
            float dx = __fsub_rn(qq.x, xq.x), dy = __fsub_rn(qq.y, xq.y);
            float dz = __fsub_rn(qq.z, xq.z), dw = __fsub_rn(qq.w, xq.w);
            lsum = fmaf(dx, dx, lsum); lsum = fmaf(dy, dy, lsum);
            lsum = fmaf(dz, dz, lsum); lsum = fmaf(dw, dw, lsum);
            float4 o;
            o.x = __fadd_rn(xq.x, dx); o.y = __fadd_rn(xq.y, dy);
            o.z = __fadd_rn(xq.z, dz); o.w = __fadd_rn(xq.w, dw);
            o4[(size_t)grow * 48 + c4] = o;
        }
    }

    // ---- loss reduction + single-kernel finalize ----
    #pragma unroll
    for (int off = 16; off > 0; off >>= 1)
        lsum += __shfl_down_sync(0xffffffffu, lsum, off);
    if (lane == 0) wred[wid] = lsum;
    __syncthreads();
    if (tid == 0) {
        float bs = 0.f;
        #pragma unroll
        for (int w = 0; w < NWARP; ++w) bs += wred[w];
        atomicAdd(&g_loss_sum, (double)bs);
        __threadfence();
        unsigned int prev = atomicAdd(&g_done, 1u);
        if (prev == gridDim.x - 1) {
            __threadfence();
            double total = atomicAdd(&g_loss_sum, 0.0);
            double mean = total / ((double)n * (double)EDIM);
            out[(size_t)n * EDIM + n]     = (float)(1.25 * mean);  // (1+BETA)*mean
            out[(size_t)n * EDIM + n + 1] = 0.0f;                  // contrastloss
            g_loss_sum = 0.0;
            g_done = 0u;
            __threadfence();
        }
    }
}

extern "C" void kernel_launch(void* const* d_in, const int* in_sizes, int n_in,
                              void* d_out, int out_size) {
    (void)n_in; (void)out_size;
    const float* x = (const float*)d_in[0];   // [N, 192] fp32
    const float* e = (const float*)d_in[1];   // [50, 192] fp32
    float* out = (float*)d_out;               // [N*192 | N | 1 | 1] fp32
    const int n = in_sizes[0] / EDIM;

    const int blocks = (n + ROWS_PER_BLOCK - 1) / ROWS_PER_BLOCK;
    vq_kernel<<<blocks, NTHREADS>>>(x, e, out, n);
}

// round 6
// speedup vs baseline: 1.4584x; 1.4584x over previous
#include <cuda_runtime.h>
#include <cstdint>

#define NJ 50
#define EDIM 192
#define NJP 56           // padded codes (4 js * 14)
#define ETSTRIDE 56      // floats per k-row of Et ([k][j] transpose, stride 56)
#define NWARP 8
#define NTHREADS 256
#define ROWS_PER_WARP 32
#define ROWS_PER_BLOCK 256

__device__ double g_loss_sum;     // zero-init at module load
__device__ unsigned int g_done;

static __device__ __forceinline__ unsigned long long pack2s(float v) {
    unsigned long long r;
    asm("mov.b64 %0, {%1, %1};" : "=l"(r) : "f"(v));
    return r;
}
static __device__ __forceinline__ void unpack2(unsigned long long v, float& lo, float& hi) {
    asm("mov.b64 {%0, %1}, %2;" : "=f"(lo), "=f"(hi) : "l"(v));
}
// Packed dual fp32 FMA (FFMA2)
static __device__ __forceinline__ unsigned long long fma2(unsigned long long a,
                                                          unsigned long long b,
                                                          unsigned long long c) {
    unsigned long long d;
    asm("fma.rn.f32x2 %0, %1, %2, %3;" : "=l"(d) : "l"(a), "l"(b), "l"(c));
    return d;
}

// Thread layout: lane = (g<<2)|js ; js in [0,4) splits codes (14 each, j = 14*js+jj),
// g in [0,8) = row group. Thread rows: base + g + 8*i, i=0..3 (4 rows/thread).
// acc f32x2 packs a CODE PAIR (2p, 2p+1) for one row -> e operand is a raw LDS.64.
__global__ void __launch_bounds__(NTHREADS, 2) vq_kernel(
        const float* __restrict__ x, const float* __restrict__ e,
        float* __restrict__ out, int n) {
    __shared__ __align__(8) float Et[EDIM * ETSTRIDE];  // Et[k*56 + j] = e[j][k], j>=50 zero
    __shared__ float see[NJP];
    __shared__ int   bjsh[ROWS_PER_BLOCK];
    __shared__ float wred[NWARP];

    const int tid = threadIdx.x;
    const int wid = tid >> 5;
    const int lane = tid & 31;
    const int js = lane & 3;
    const int g = lane >> 2;

    // ---- init: zero Et, fill transpose, see (+inf pads) ----
    for (int i = tid; i < EDIM * ETSTRIDE; i += NTHREADS) Et[i] = 0.f;
    __syncthreads();
    for (int i = tid; i < NJ * EDIM; i += NTHREADS) {
        int j = i / EDIM, k = i - j * EDIM;        // e[j][k] coalesced read
        Et[k * ETSTRIDE + j] = e[i];
    }
    if (tid < NJP) {
        float s = 3.402823466e38f;
        if (tid < NJ) {
            s = 0.f;
            const float* ej = e + (size_t)tid * EDIM;
            #pragma unroll 4
            for (int k = 0; k < EDIM; ++k) { float v = __ldg(ej + k); s = fmaf(v, v, s); }
        }
        see[tid] = s;
    }
    __syncthreads();

    const int tile_base = blockIdx.x * ROWS_PER_BLOCK;
    const int warpbase = wid * ROWS_PER_WARP;
    int rows[4];
    #pragma unroll
    for (int i = 0; i < 4; ++i) {
        int r = tile_base + warpbase + g + 8 * i;
        rows[i] = (r < n) ? r : (n - 1);
    }

    // ---- accumulate 4 rows x 7 code-pairs + per-row ||x||^2 (R2's exact chain) ----
    unsigned long long acc[4][7];
    float s0[4], s1[4];
    #pragma unroll
    for (int i = 0; i < 4; ++i) {
        s0[i] = 0.f; s1[i] = 0.f;
        #pragma unroll
        for (int p = 0; p < 7; ++p) acc[i][p] = 0ULL;
    }

    const float4* x4 = reinterpret_cast<const float4*>(x);
    const int ebase = 14 * js;

    #pragma unroll 1
    for (int kq = 0; kq < EDIM / 4; ++kq) {
        float4 xv[4];
        #pragma unroll
        for (int i = 0; i < 4; ++i) xv[i] = __ldg(x4 + (size_t)rows[i] * 48 + kq);

        #pragma unroll
        for (int c = 0; c < 4; ++c) {
            const int k = kq * 4 + c;
            const unsigned long long* ep =
                reinterpret_cast<const unsigned long long*>(&Et[k * ETSTRIDE + ebase]);
            float a0, a1, a2, a3;
            if (c == 0)      { a0 = xv[0].x; a1 = xv[1].x; a2 = xv[2].x; a3 = xv[3].x; }
            else if (c == 1) { a0 = xv[0].y; a1 = xv[1].y; a2 = xv[2].y; a3 = xv[3].y; }
            else if (c == 2) { a0 = xv[0].z; a1 = xv[1].z; a2 = xv[2].z; a3 = xv[3].z; }
            else             { a0 = xv[0].w; a1 = xv[1].w; a2 = xv[2].w; a3 = xv[3].w; }
            // ||x||^2 partials: comps x,z -> s0 ; y,w -> s1 (R2's exact order)
            if ((c & 1) == 0) {
                s0[0] = fmaf(a0, a0, s0[0]); s0[1] = fmaf(a1, a1, s0[1]);
                s0[2] = fmaf(a2, a2, s0[2]); s0[3] = fmaf(a3, a3, s0[3]);
            } else {
                s1[0] = fmaf(a0, a0, s1[0]); s1[1] = fmaf(a1, a1, s1[1]);
                s1[2] = fmaf(a2, a2, s1[2]); s1[3] = fmaf(a3, a3, s1[3]);
            }
            const unsigned long long xp0 = pack2s(a0), xp1 = pack2s(a1);
            const unsigned long long xp2 = pack2s(a2), xp3 = pack2s(a3);
            #pragma unroll
            for (int p = 0; p < 7; ++p) {
                const unsigned long long ev = ep[p];   // LDS.64: codes (2p, 2p+1)
                acc[0][p] = fma2(xp0, ev, acc[0][p]);
                acc[1][p] = fma2(xp1, ev, acc[1][p]);
                acc[2][p] = fma2(xp2, ev, acc[2][p]);
                acc[3][p] = fma2(xp3, ev, acc[3][p]);
            }
        }
    }

    // ---- per-thread argmin (exact R2 compare), then combine over 4 js-lanes ----
    #pragma unroll
    for (int i = 0; i < 4; ++i) {
        const float sxx = s0[i] + s1[i];
        float v = 3.402823466e38f;
        int jx = 0;
        #pragma unroll
        for (int p = 0; p < 7; ++p) {
            float dlo, dhi;
            unpack2(acc[i][p], dlo, dhi);
            const int j = ebase + 2 * p;
            float mlo = __fsub_rn(__fadd_rn(sxx, see[j]),     2.0f * dlo);
            float mhi = __fsub_rn(__fadd_rn(sxx, see[j + 1]), 2.0f * dhi);
            if (mlo < v) { v = mlo; jx = j; }
            if (mhi < v) { v = mhi; jx = j + 1; }
        }
        #pragma unroll
        for (int mask = 1; mask <= 2; mask <<= 1) {
            float ov = __shfl_xor_sync(0xffffffffu, v, mask);
            int   oj = __shfl_xor_sync(0xffffffffu, jx, mask);
            if (ov < v || (ov == v && oj < jx)) { v = ov; jx = oj; }
        }
        const int grow = tile_base + warpbase + g + 8 * i;
        if (js == 0) {
            bjsh[warpbase + g + 8 * i] = jx;
            if (grow < n) out[(size_t)n * EDIM + grow] = (float)jx;
        }
    }
    __syncwarp();

    // ---- phase 2: warp-cooperative coalesced straight-through write + loss ----
    float lsum = 0.f;
    const float4* e4 = reinterpret_cast<const float4*>(e);
    float4* o4 = reinterpret_cast<float4*>(out);
    #pragma unroll 4
    for (int it = 0; it < (ROWS_PER_WARP * 48) / 32; ++it) {   // 48 iters
        const int idx = it * 32 + lane;
        const int rl = idx / 48, c4 = idx - rl * 48;
        const int grow = tile_base + warpbase + rl;
        if (grow < n) {
            const int bj = bjsh[warpbase + rl];
            const float4 xq = __ldg(x4 + (size_t)grow * 48 + c4);
            const float4 qq = __ldg(e4 + (size_t)bj * 48 + c4);
            float dx = __fsub_rn(qq.x, xq.x), dy = __fsub_rn(qq.y, xq.y);
            float dz = __fsub_rn(qq.z, xq.z), dw = __fsub_rn(qq.w, xq.w);
            lsum = fmaf(dx, dx, lsum); lsum = fmaf(dy, dy, lsum);
            lsum = fmaf(dz, dz, lsum); lsum = fmaf(dw, dw, lsum);
            float4 o;
            o.x = __fadd_rn(xq.x, dx); o.y = __fadd_rn(xq.y, dy);
            o.z = __fadd_rn(xq.z, dz); o.w = __fadd_rn(xq.w, dw);
            o4[(size_t)grow * 48 + c4] = o;
        }
    }

    // ---- loss reduction + single-kernel finalize ----
    #pragma unroll
    for (int off = 16; off > 0; off >>= 1)
        lsum += __shfl_down_sync(0xffffffffu, lsum, off);
    if (lane == 0) wred[wid] = lsum;
    __syncthreads();
    if (tid == 0) {
        float bs = 0.f;
        #pragma unroll
        for (int w = 0; w < NWARP; ++w) bs += wred[w];
        atomicAdd(&g_loss_sum, (double)bs);
        __threadfence();
        unsigned int prev = atomicAdd(&g_done, 1u);
        if (prev == gridDim.x - 1) {
            __threadfence();
            double total = atomicAdd(&g_loss_sum, 0.0);
            double mean = total / ((double)n * (double)EDIM);
            out[(size_t)n * EDIM + n]     = (float)(1.25 * mean);  // (1+BETA)*mean
            out[(size_t)n * EDIM + n + 1] = 0.0f;                  // contrastloss
            g_loss_sum = 0.0;
            g_done = 0u;
            __threadfence();
        }
    }
}

extern "C" void kernel_launch(void* const* d_in, const int* in_sizes, int n_in,
                              void* d_out, int out_size) {
    (void)n_in; (void)out_size;
    const float* x = (const float*)d_in[0];   // [N, 192] fp32
    const float* e = (const float*)d_in[1];   // [50, 192] fp32
    float* out = (float*)d_out;               // [N*192 | N | 1 | 1] fp32
    const int n = in_sizes[0] / EDIM;

    const int blocks = (n + ROWS_PER_BLOCK - 1) / ROWS_PER_BLOCK;
    vq_kernel<<<blocks, NTHREADS>>>(x, e, out, n);
}